// round 16
// baseline (speedup 1.0000x reference)
#include <cuda_runtime.h>
#include <cuda_fp16.h>
#include <math.h>
#include <stdint.h>

// ---------------------------------------------------------------------------
// Problem constants
// ---------------------------------------------------------------------------
#define BATCH   8192
#define DIN     5169      // 1723*3
#define DINP    5184      // padded to 64
#define DH      1024
#define DOUT    226
#define DOUTP   256
#define EPS     1e-5f

// GEMM tiling: block 128x64, 256 threads (8 warps), warp tile 32x32 (4m x 2n)
// 2 blocks/SM co-residency; persistent blocks + dynamic tile stealing
#define BM      128
#define BN      64
#define BK      64
#define NTHREADS 256
#define OFF_A1  0
#define OFF_A2  16384
#define OFF_B1  32768
#define OFF_B2  40960
#define STAGE   49152
#define SMEM_REQ (2*STAGE + 16)   // + tile-broadcast slot; 2 blocks/SM
#define PERSIST_BLOCKS 296        // 2 x 148 SMs

__device__ __forceinline__ uint32_t smem_u32(const void* p) {
    uint32_t a;
    asm("{ .reg .u64 t; cvta.to.shared.u64 t, %1; cvt.u32.u64 %0, t; }" : "=r"(a) : "l"(p));
    return a;
}

#define CPA16(dst, src) asm volatile("cp.async.cg.shared.global [%0], [%1], 16;" :: "r"(dst), "l"(src) : "memory")
#define CP_COMMIT() asm volatile("cp.async.commit_group;" ::: "memory")
#define CP_WAIT1()  asm volatile("cp.async.wait_group 1;" ::: "memory")
#define CP_WAIT0()  asm volatile("cp.async.wait_group 0;" ::: "memory")

#define LDSM4(r, addr) \
    asm volatile("ldmatrix.sync.aligned.m8n8.x4.shared.b16 {%0,%1,%2,%3}, [%4];" \
        : "=r"((r)[0]), "=r"((r)[1]), "=r"((r)[2]), "=r"((r)[3]) : "r"(addr))

#define MMA16816(c, a, b) \
    asm volatile("mma.sync.aligned.m16n8k16.row.col.f32.f16.f16.f32 " \
        "{%0,%1,%2,%3}, {%4,%5,%6,%7}, {%8,%9}, {%0,%1,%2,%3};" \
        : "+f"((c)[0]), "+f"((c)[1]), "+f"((c)[2]), "+f"((c)[3]) \
        : "r"((a)[0]), "r"((a)[1]), "r"((a)[2]), "r"((a)[3]), \
          "r"((b)[0]), "r"((b)[1]))

// ---------------------------------------------------------------------------
// Device scratch
// ---------------------------------------------------------------------------
__device__ float g_Y[BATCH * DH];
__device__ float g_O[BATCH * DOUT];
__device__ float g_stats[12 * DH];    // [layer][sum|sumsq][DH], 6 layers
__device__ int   g_tileCtr[8];        // per-GEMM tile counters

// 2-way fp16 splits for activations
__device__ __half g_A01[BATCH * DINP];
__device__ __half g_A02[BATCH * DINP];
__device__ __half g_H1[BATCH * DH];
__device__ __half g_H2[BATCH * DH];
__device__ __half g_T1[BATCH * DH];
__device__ __half g_T2[BATCH * DH];

// 2-way fp16 splits for weights (transposed [N][K])
__device__ __half g_W0s[2][DH * DINP];
__device__ __half g_W1as[2][DH * DH];
__device__ __half g_W1bs[2][DH * DH];
__device__ __half g_W2as[2][DH * DH];
__device__ __half g_W2bs[2][DH * DH];
__device__ __half g_W3s[2][DOUTP * DH];

// ---------------------------------------------------------------------------
// Mega-prep: input split + all 6 weight transposes + stat/counter zeroing.
// ---------------------------------------------------------------------------
#define TB_SPLIT ((BATCH * DINP / 8 + 255) / 256)   // 20736
#define TB_W0   5184
#define TB_MID  1024
#define TB_W3   256
#define TB_ZERO 49
#define TB_TOTAL (TB_SPLIT + TB_W0 + 4*TB_MID + TB_W3 + TB_ZERO)

__device__ __forceinline__ void transpose_tile(
    const float* __restrict__ W, __half* __restrict__ s1, __half* __restrict__ s2,
    int K, int N, int Kpad, int tileKx, int localBid, int tx, int ty)
{
    __shared__ float sh[32][33];
    int kt = localBid % tileKx, nt = localBid / tileKx;
    int k0 = kt * 32, n0 = nt * 32;
#pragma unroll
    for (int p = 0; p < 4; p++) {
        int k = k0 + ty + p * 8, n = n0 + tx;
        sh[ty + p * 8][tx] = (k < K && n < N) ? W[(size_t)k * N + n] : 0.f;
    }
    __syncthreads();
#pragma unroll
    for (int p = 0; p < 4; p++) {
        int no = n0 + ty + p * 8, ko = k0 + tx;
        float v = sh[tx][ty + p * 8];
        __half h1 = __float2half(v);
        size_t idx = (size_t)no * Kpad + ko;
        s1[idx] = h1;
        s2[idx] = __float2half(v - __half2float(h1));
    }
}

__global__ void __launch_bounds__(256) mega_prep(
    const float* __restrict__ V,
    const float* __restrict__ W0, const float* __restrict__ W1a,
    const float* __restrict__ W1b, const float* __restrict__ W2a,
    const float* __restrict__ W2b, const float* __restrict__ W3)
{
    int bid = blockIdx.x;
    if (bid < TB_SPLIT) {
        int i = bid * 256 + threadIdx.x;
        int total8 = BATCH * DINP / 8;
        if (i >= total8) return;
        int cp8 = DINP >> 3;
        int r = i / cp8, c0 = (i - r * cp8) << 3;
        const float* row = V + (size_t)r * DIN;
        union { __half h[8]; uint4 u; } p1, p2;
#pragma unroll
        for (int k = 0; k < 8; k++) {
            int c = c0 + k;
            float v = (c < DIN) ? row[c] : 0.f;
            __half h1 = __float2half(v);
            p1.h[k] = h1;
            p2.h[k] = __float2half(v - __half2float(h1));
        }
        reinterpret_cast<uint4*>(g_A01)[i] = p1.u;
        reinterpret_cast<uint4*>(g_A02)[i] = p2.u;
        return;
    }
    bid -= TB_SPLIT;

    int tx = threadIdx.x & 31, ty = threadIdx.x >> 5;
    if (bid < TB_W0) {
        transpose_tile(W0, g_W0s[0], g_W0s[1], DIN, DH, DINP, DINP / 32, bid, tx, ty);
        return;
    }
    bid -= TB_W0;
    if (bid < TB_MID) {
        transpose_tile(W1a, g_W1as[0], g_W1as[1], DH, DH, DH, DH / 32, bid, tx, ty);
        return;
    }
    bid -= TB_MID;
    if (bid < TB_MID) {
        transpose_tile(W1b, g_W1bs[0], g_W1bs[1], DH, DH, DH, DH / 32, bid, tx, ty);
        return;
    }
    bid -= TB_MID;
    if (bid < TB_MID) {
        transpose_tile(W2a, g_W2as[0], g_W2as[1], DH, DH, DH, DH / 32, bid, tx, ty);
        return;
    }
    bid -= TB_MID;
    if (bid < TB_MID) {
        transpose_tile(W2b, g_W2bs[0], g_W2bs[1], DH, DH, DH, DH / 32, bid, tx, ty);
        return;
    }
    bid -= TB_MID;
    if (bid < TB_W3) {
        transpose_tile(W3, g_W3s[0], g_W3s[1], DH, DOUT, DH, DH / 32, bid, tx, ty);
        return;
    }
    bid -= TB_W3;
    int i = bid * 256 + threadIdx.x;
    if (i < 12 * DH) g_stats[i] = 0.f;
    int j = i - 12 * DH;
    if (j >= 0 && j < 8) g_tileCtr[j] = 0;
}

// ---------------------------------------------------------------------------
// Persistent mma.sync 2-split fp16 GEMM (dynamic tile stealing):
//   C[M][ldC] = A(M x Kpad) * B^T(Npad x Kpad) + bias
// main acc: a1b1.  corr acc: a2b1, a1b2.
// Fused column stats via warp-shuffle reduction + global atomics.
// ---------------------------------------------------------------------------
__device__ __forceinline__ void prefetch_stage(
    uint32_t s0,
    const __half* __restrict__ A1, const __half* __restrict__ A2,
    const __half* __restrict__ B1, const __half* __restrict__ B2,
    int row0, int col0, size_t Kpad, size_t kb, int tid)
{
#pragma unroll
    for (int i = 0; i < 4; i++) {
        int idx = i * NTHREADS + tid;
        int r = idx >> 3, c8 = idx & 7;
        uint32_t dst = (uint32_t)(r * 128 + ((c8 ^ (r & 7)) << 4));
        size_t g = (size_t)(row0 + r) * Kpad + kb + (size_t)c8 * 8;
        CPA16(s0 + OFF_A1 + dst, A1 + g);
        CPA16(s0 + OFF_A2 + dst, A2 + g);
    }
#pragma unroll
    for (int i = 0; i < 2; i++) {
        int idx = i * NTHREADS + tid;
        int r = idx >> 3, c8 = idx & 7;
        uint32_t dst = (uint32_t)(r * 128 + ((c8 ^ (r & 7)) << 4));
        size_t g = (size_t)(col0 + r) * Kpad + kb + (size_t)c8 * 8;
        CPA16(s0 + OFF_B1 + dst, B1 + g);
        CPA16(s0 + OFF_B2 + dst, B2 + g);
    }
    CP_COMMIT();
}

__global__ void __launch_bounds__(NTHREADS, 2) gemm_mma_split2(
    const __half* __restrict__ A1, const __half* __restrict__ A2,
    const __half* __restrict__ B1, const __half* __restrict__ B2,
    const float* __restrict__ bias, float* __restrict__ C,
    int Kpad, int Nreal, int ldC,
    float* __restrict__ statSum, float* __restrict__ statSq,
    int* __restrict__ tileCtr, int nTx, int nTy)
{
    extern __shared__ char smraw[];
    const uint32_t sb = smem_u32(smraw);
    int* s_tile = reinterpret_cast<int*>(smraw + 2 * STAGE);

    const int tid = threadIdx.x, wid = tid >> 5, lane = tid & 31;
    const int wm = (wid >> 1) * 32;
    const int wn = (wid & 1) * 32;
    const int T = Kpad / BK;
    const int nTiles = nTx * nTy;

    const int la_r  = (lane & 7) + (lane & 8);
    const int la_kh = (lane & 16) ? 8 : 0;
    const int lb_r  = (lane & 7) + ((lane & 16) ? 8 : 0);
    const int lb_kh = (lane & 8) ? 8 : 0;
    const int gid = lane >> 2, tig = lane & 3;
    const bool doStats = (statSum != nullptr);

    for (;;) {
        if (tid == 0) *s_tile = atomicAdd(tileCtr, 1);
        __syncthreads();
        const int tile = *s_tile;
        __syncthreads();
        if (tile >= nTiles) break;
        const int col0 = (tile % nTx) * BN;
        const int row0 = (tile / nTx) * BM;

        float am[2][4][4];
        float ac[2][4][4];
#pragma unroll
        for (int i = 0; i < 2; i++)
#pragma unroll
            for (int j = 0; j < 4; j++)
#pragma unroll
                for (int v = 0; v < 4; v++) { am[i][j][v] = 0.f; ac[i][j][v] = 0.f; }

        prefetch_stage(sb, A1, A2, B1, B2, row0, col0, (size_t)Kpad, 0, tid);

        for (int t = 0; t < T; t++) {
            if (t + 1 < T) {
                prefetch_stage(sb + ((t + 1) & 1) * STAGE, A1, A2, B1, B2,
                               row0, col0, (size_t)Kpad, (size_t)(t + 1) * BK, tid);
                CP_WAIT1();
            } else {
                CP_WAIT0();
            }
            __syncthreads();

            const uint32_t s0 = sb + (t & 1) * STAGE;
#pragma unroll
            for (int ks = 0; ks < 4; ks++) {
                uint32_t a1[2][4], a2[2][4];
#pragma unroll
                for (int i = 0; i < 2; i++) {
                    int r = wm + 16 * i + la_r;
                    int k = ks * 16 + la_kh;
                    uint32_t addr = s0 + OFF_A1 + r * 128 + ((((k >> 3) ^ r) & 7) << 4);
                    LDSM4(a1[i], addr);
                    LDSM4(a2[i], addr + (OFF_A2 - OFF_A1));
                }
                const int rB = wn + lb_r;
                const int kB = ks * 16 + lb_kh;
                const uint32_t baddr0 = s0 + OFF_B1 + rB * 128 + ((((kB >> 3) ^ rB) & 7) << 4);
                const uint32_t baddr1 = s0 + OFF_B1 + (rB + 16) * 128 + ((((kB >> 3) ^ (rB + 16)) & 7) << 4);

                {
                    uint32_t b[4][2], q[4];
                    LDSM4(q, baddr0);
                    b[0][0]=q[0]; b[0][1]=q[1]; b[1][0]=q[2]; b[1][1]=q[3];
                    LDSM4(q, baddr1);
                    b[2][0]=q[0]; b[2][1]=q[1]; b[3][0]=q[2]; b[3][1]=q[3];
#pragma unroll
                    for (int i = 0; i < 2; i++)
#pragma unroll
                        for (int j = 0; j < 4; j++) {
                            MMA16816(am[i][j], a1[i], b[j]);
                            MMA16816(ac[i][j], a2[i], b[j]);
                        }
                }
                {
                    uint32_t b[4][2], q[4];
                    LDSM4(q, baddr0 + (OFF_B2 - OFF_B1));
                    b[0][0]=q[0]; b[0][1]=q[1]; b[1][0]=q[2]; b[1][1]=q[3];
                    LDSM4(q, baddr1 + (OFF_B2 - OFF_B1));
                    b[2][0]=q[0]; b[2][1]=q[1]; b[3][0]=q[2]; b[3][1]=q[3];
#pragma unroll
                    for (int i = 0; i < 2; i++)
#pragma unroll
                        for (int j = 0; j < 4; j++)
                            MMA16816(ac[i][j], a1[i], b[j]);
                }
            }
            __syncthreads();
        }

        // epilogue
#pragma unroll
        for (int j = 0; j < 4; j++) {
            int cc = col0 + wn + 8 * j + tig * 2;
            float se = 0.f, so = 0.f, qe = 0.f, qo = 0.f;
            if (cc < Nreal) {
                float b0 = bias[cc], b1 = bias[cc + 1];
#pragma unroll
                for (int i = 0; i < 2; i++) {
                    int r = row0 + wm + 16 * i + gid;
                    float v00 = am[i][j][0] + ac[i][j][0] + b0;
                    float v01 = am[i][j][1] + ac[i][j][1] + b1;
                    float v10 = am[i][j][2] + ac[i][j][2] + b0;
                    float v11 = am[i][j][3] + ac[i][j][3] + b1;
                    *reinterpret_cast<float2*>(C + (size_t)r * ldC + cc) = make_float2(v00, v01);
                    *reinterpret_cast<float2*>(C + (size_t)(r + 8) * ldC + cc) = make_float2(v10, v11);
                    se += v00 + v10;
                    so += v01 + v11;
                    qe += fmaf(v00, v00, v10 * v10);
                    qo += fmaf(v01, v01, v11 * v11);
                }
            }
            if (doStats) {
#pragma unroll
                for (int m = 4; m <= 16; m <<= 1) {
                    se += __shfl_xor_sync(0xFFFFFFFFu, se, m);
                    so += __shfl_xor_sync(0xFFFFFFFFu, so, m);
                    qe += __shfl_xor_sync(0xFFFFFFFFu, qe, m);
                    qo += __shfl_xor_sync(0xFFFFFFFFu, qo, m);
                }
                if (gid == 0) {
                    atomicAdd(&statSum[cc],     se);
                    atomicAdd(&statSum[cc + 1], so);
                    atomicAdd(&statSq[cc],      qe);
                    atomicAdd(&statSq[cc + 1],  qo);
                }
            }
        }
        __syncthreads();   // all done reading s_tile / smem before next iteration
    }
}

// ---------------------------------------------------------------------------
// Fused BN finalize + apply (4096 blocks x 2 rows, batched loads):
// ---------------------------------------------------------------------------
#define APPLY_BLOCKS 4096
#define APPLY_ROWS   (BATCH / APPLY_BLOCKS)   // 2

__global__ void __launch_bounds__(256) apply_bn_fused(
    const float4* __restrict__ Y4,
    const uint2* __restrict__ r1In,
    const uint2* __restrict__ r2In,
    uint2* __restrict__ o1,
    uint2* __restrict__ o2,
    const float* __restrict__ stat,
    const float* __restrict__ g,
    const float* __restrict__ be,
    int has_res)
{
    const int t = threadIdx.x;
    const int r0 = blockIdx.x * APPLY_ROWS;
    const int idx0 = r0 * (DH / 4) + t;
    const int idx1 = idx0 + (DH / 4);

    float4 y0 = Y4[idx0];
    float4 y1 = Y4[idx1];
    uint2 q10 = make_uint2(0u, 0u), q20 = make_uint2(0u, 0u);
    uint2 q11 = make_uint2(0u, 0u), q21 = make_uint2(0u, 0u);
    if (has_res) {
        q10 = r1In[idx0]; q20 = r2In[idx0];
        q11 = r1In[idx1]; q21 = r2In[idx1];
    }
    float4 sm = reinterpret_cast<const float4*>(stat)[t];
    float4 sq = reinterpret_cast<const float4*>(stat + DH)[t];
    float4 gg = reinterpret_cast<const float4*>(g)[t];
    float4 bb = reinterpret_cast<const float4*>(be)[t];

    const float invM = 1.f / (float)BATCH;
    float m0 = sm.x * invM, m1 = sm.y * invM, m2 = sm.z * invM, m3 = sm.w * invM;
    float a0 = gg.x * rsqrtf(sq.x * invM - m0 * m0 + EPS);
    float a1 = gg.y * rsqrtf(sq.y * invM - m1 * m1 + EPS);
    float a2 = gg.z * rsqrtf(sq.z * invM - m2 * m2 + EPS);
    float a3 = gg.w * rsqrtf(sq.w * invM - m3 * m3 + EPS);
    float c0 = bb.x - a0 * m0;
    float c1 = bb.y - a1 * m1;
    float c2 = bb.z - a2 * m2;
    float c3 = bb.w - a3 * m3;

    {
        union { __half h[4]; uint2 u; } q1, q2, p1, p2;
        q1.u = q10; q2.u = q20;
        float o[4];
        o[0] = fmaf(a0, y0.x, c0); o[1] = fmaf(a1, y0.y, c1);
        o[2] = fmaf(a2, y0.z, c2); o[3] = fmaf(a3, y0.w, c3);
        if (has_res) {
            o[0] += __half2float(q1.h[0]) + __half2float(q2.h[0]);
            o[1] += __half2float(q1.h[1]) + __half2float(q2.h[1]);
            o[2] += __half2float(q1.h[2]) + __half2float(q2.h[2]);
            o[3] += __half2float(q1.h[3]) + __half2float(q2.h[3]);
        }
#pragma unroll
        for (int v = 0; v < 4; v++) {
            float ov = fmaxf(0.f, o[v]);
            __half h1 = __float2half(ov);
            p1.h[v] = h1;
            p2.h[v] = __float2half(ov - __half2float(h1));
        }
        o1[idx0] = p1.u;
        o2[idx0] = p2.u;
    }
    {
        union { __half h[4]; uint2 u; } q1, q2, p1, p2;
        q1.u = q11; q2.u = q21;
        float o[4];
        o[0] = fmaf(a0, y1.x, c0); o[1] = fmaf(a1, y1.y, c1);
        o[2] = fmaf(a2, y1.z, c2); o[3] = fmaf(a3, y1.w, c3);
        if (has_res) {
            o[0] += __half2float(q1.h[0]) + __half2float(q2.h[0]);
            o[1] += __half2float(q1.h[1]) + __half2float(q2.h[1]);
            o[2] += __half2float(q1.h[2]) + __half2float(q2.h[2]);
            o[3] += __half2float(q1.h[3]) + __half2float(q2.h[3]);
        }
#pragma unroll
        for (int v = 0; v < 4; v++) {
            float ov = fmaxf(0.f, o[v]);
            __half h1 = __float2half(ov);
            p1.h[v] = h1;
            p2.h[v] = __float2half(ov - __half2float(h1));
        }
        o1[idx1] = p1.u;
        o2[idx1] = p2.u;
    }
}

// ---------------------------------------------------------------------------
// Polar decomposition of 3x3 (== U*Vh), times sign(det) + betas passthrough
// ---------------------------------------------------------------------------
__device__ __forceinline__ void cof3(const float* X, float* C) {
    C[0] = X[4]*X[8] - X[5]*X[7];
    C[1] = X[5]*X[6] - X[3]*X[8];
    C[2] = X[3]*X[7] - X[4]*X[6];
    C[3] = X[2]*X[7] - X[1]*X[8];
    C[4] = X[0]*X[8] - X[2]*X[6];
    C[5] = X[1]*X[6] - X[0]*X[7];
    C[6] = X[1]*X[5] - X[2]*X[4];
    C[7] = X[2]*X[3] - X[0]*X[5];
    C[8] = X[0]*X[4] - X[1]*X[3];
}

__global__ void polar_betas_kernel(const float* __restrict__ O, float* __restrict__ out) {
    int n = blockIdx.x * blockDim.x + threadIdx.x;
    if (n >= BATCH * 24) {
        int i = n - BATCH * 24;
        if (i < BATCH * 10) {
            int r = i / 10, j = i % 10;
            out[(size_t)BATCH * 216 + i] = O[(size_t)r * DOUT + 216 + j];
        }
        return;
    }
    int r = n / 24, m = n % 24;
    const float* src = O + (size_t)r * DOUT + m * 9;
    float X[9];
#pragma unroll
    for (int i = 0; i < 9; i++) X[i] = src[i];

    float C[9];
    cof3(X, C);
    float det0 = X[0]*C[0] + X[1]*C[1] + X[2]*C[2];
    float sgn = (det0 >= 0.f) ? 1.f : -1.f;

    float fro = 0.f;
#pragma unroll
    for (int i = 0; i < 9; i++) fro = fmaf(X[i], X[i], fro);
    float inv = rsqrtf(fmaxf(fro, 1e-30f));
#pragma unroll
    for (int i = 0; i < 9; i++) X[i] *= inv;

#pragma unroll
    for (int it = 0; it < 12; it++) {
        cof3(X, C);
        float det = X[0]*C[0] + X[1]*C[1] + X[2]*C[2];
        float adet = fabsf(det);
        if (adet < 1e-30f) break;
        float gscale = rcbrtf(adet);
        float invdet = 1.f / det;
        float ig = 0.5f * invdet / gscale;
        float hg = 0.5f * gscale;
#pragma unroll
        for (int i = 0; i < 9; i++) X[i] = hg * X[i] + ig * C[i];
    }

    float* dst = out + (size_t)n * 9;
#pragma unroll
    for (int i = 0; i < 9; i++) dst[i] = X[i] * sgn;
}

// ---------------------------------------------------------------------------
// Launch
// ---------------------------------------------------------------------------
extern "C" void kernel_launch(void* const* d_in, const int* in_sizes, int n_in,
                              void* d_out, int out_size)
{
    const float* V   = (const float*)d_in[0];
    const float* W0  = (const float*)d_in[1];
    const float* b0  = (const float*)d_in[2];
    const float* g0  = (const float*)d_in[3];
    const float* be0 = (const float*)d_in[4];
    const float* W1a = (const float*)d_in[5];
    const float* b1a = (const float*)d_in[6];
    const float* g1a = (const float*)d_in[7];
    const float* be1a= (const float*)d_in[8];
    const float* W1b = (const float*)d_in[9];
    const float* b1b = (const float*)d_in[10];
    const float* g1b = (const float*)d_in[11];
    const float* be1b= (const float*)d_in[12];
    const float* W2a = (const float*)d_in[13];
    const float* b2a = (const float*)d_in[14];
    const float* g2a = (const float*)d_in[15];
    const float* be2a= (const float*)d_in[16];
    const float* W2b = (const float*)d_in[17];
    const float* b2b = (const float*)d_in[18];
    const float* g2b = (const float*)d_in[19];
    const float* be2b= (const float*)d_in[20];
    const float* W3  = (const float*)d_in[21];
    const float* b3  = (const float*)d_in[22];

    float *Y, *O, *ST;
    int *TC;
    cudaGetSymbolAddress((void**)&Y, g_Y);
    cudaGetSymbolAddress((void**)&O, g_O);
    cudaGetSymbolAddress((void**)&ST, g_stats);
    cudaGetSymbolAddress((void**)&TC, g_tileCtr);

    __half *A0s[2], *Hs[2], *Ts[2];
    __half *W0p[2], *W1ap[2], *W1bp[2], *W2ap[2], *W2bp[2], *W3p[2];
    {
        __half* base;
        cudaGetSymbolAddress((void**)&base, g_A01); A0s[0] = base;
        cudaGetSymbolAddress((void**)&base, g_A02); A0s[1] = base;
        cudaGetSymbolAddress((void**)&base, g_H1);  Hs[0] = base;
        cudaGetSymbolAddress((void**)&base, g_H2);  Hs[1] = base;
        cudaGetSymbolAddress((void**)&base, g_T1);  Ts[0] = base;
        cudaGetSymbolAddress((void**)&base, g_T2);  Ts[1] = base;
        cudaGetSymbolAddress((void**)&base, g_W0s);
        W0p[0] = base; W0p[1] = base + (size_t)DH * DINP;
        cudaGetSymbolAddress((void**)&base, g_W1as);
        W1ap[0] = base; W1ap[1] = base + (size_t)DH * DH;
        cudaGetSymbolAddress((void**)&base, g_W1bs);
        W1bp[0] = base; W1bp[1] = base + (size_t)DH * DH;
        cudaGetSymbolAddress((void**)&base, g_W2as);
        W2ap[0] = base; W2ap[1] = base + (size_t)DH * DH;
        cudaGetSymbolAddress((void**)&base, g_W2bs);
        W2bp[0] = base; W2bp[1] = base + (size_t)DH * DH;
        cudaGetSymbolAddress((void**)&base, g_W3s);
        W3p[0] = base; W3p[1] = base + (size_t)DOUTP * DH;
    }

    cudaFuncSetAttribute(gemm_mma_split2, cudaFuncAttributeMaxDynamicSharedMemorySize, SMEM_REQ);

    // ---- prep: ONE kernel (input split + weight transposes + zeroing) ----
    mega_prep<<<TB_TOTAL, 256>>>(V, W0, W1a, W1b, W2a, W2b, W3);

    const int nTx = DH / BN;        // 16
    const int nTy = BATCH / BM;     // 64
    const int nTx3 = DOUTP / BN;    // 4

    // layer 0
    gemm_mma_split2<<<PERSIST_BLOCKS, NTHREADS, SMEM_REQ>>>(
        A0s[0], A0s[1], W0p[0], W0p[1], b0, Y, DINP, DH, DH,
        ST + 0 * 2 * DH, ST + (0 * 2 + 1) * DH, TC + 0, nTx, nTy);
    apply_bn_fused<<<APPLY_BLOCKS, 256>>>((const float4*)Y, nullptr, nullptr,
                                          (uint2*)Hs[0], (uint2*)Hs[1],
                                          ST + 0 * 2 * DH, g0, be0, 0);
    // block 1
    gemm_mma_split2<<<PERSIST_BLOCKS, NTHREADS, SMEM_REQ>>>(
        Hs[0], Hs[1], W1ap[0], W1ap[1], b1a, Y, DH, DH, DH,
        ST + 1 * 2 * DH, ST + (1 * 2 + 1) * DH, TC + 1, nTx, nTy);
    apply_bn_fused<<<APPLY_BLOCKS, 256>>>((const float4*)Y, nullptr, nullptr,
                                          (uint2*)Ts[0], (uint2*)Ts[1],
                                          ST + 1 * 2 * DH, g1a, be1a, 0);
    gemm_mma_split2<<<PERSIST_BLOCKS, NTHREADS, SMEM_REQ>>>(
        Ts[0], Ts[1], W1bp[0], W1bp[1], b1b, Y, DH, DH, DH,
        ST + 2 * 2 * DH, ST + (2 * 2 + 1) * DH, TC + 2, nTx, nTy);
    apply_bn_fused<<<APPLY_BLOCKS, 256>>>((const float4*)Y, (const uint2*)Hs[0], (const uint2*)Hs[1],
                                          (uint2*)Hs[0], (uint2*)Hs[1],
                                          ST + 2 * 2 * DH, g1b, be1b, 1);
    // block 2
    gemm_mma_split2<<<PERSIST_BLOCKS, NTHREADS, SMEM_REQ>>>(
        Hs[0], Hs[1], W2ap[0], W2ap[1], b2a, Y, DH, DH, DH,
        ST + 3 * 2 * DH, ST + (3 * 2 + 1) * DH, TC + 3, nTx, nTy);
    apply_bn_fused<<<APPLY_BLOCKS, 256>>>((const float4*)Y, nullptr, nullptr,
                                          (uint2*)Ts[0], (uint2*)Ts[1],
                                          ST + 3 * 2 * DH, g2a, be2a, 0);
    gemm_mma_split2<<<PERSIST_BLOCKS, NTHREADS, SMEM_REQ>>>(
        Ts[0], Ts[1], W2bp[0], W2bp[1], b2b, Y, DH, DH, DH,
        ST + 4 * 2 * DH, ST + (4 * 2 + 1) * DH, TC + 4, nTx, nTy);
    apply_bn_fused<<<APPLY_BLOCKS, 256>>>((const float4*)Y, (const uint2*)Hs[0], (const uint2*)Hs[1],
                                          (uint2*)Hs[0], (uint2*)Hs[1],
                                          ST + 4 * 2 * DH, g2b, be2b, 1);
    // head (no stats)
    gemm_mma_split2<<<PERSIST_BLOCKS, NTHREADS, SMEM_REQ>>>(
        Hs[0], Hs[1], W3p[0], W3p[1], b3, O, DH, DOUT, DOUT,
        nullptr, nullptr, TC + 5, nTx3, nTy);

    polar_betas_kernel<<<(BATCH * 24 + BATCH * 10 + 255) / 256, 256>>>(O, (float*)d_out);
}

// round 17
// speedup vs baseline: 1.0125x; 1.0125x over previous
#include <cuda_runtime.h>
#include <cuda_fp16.h>
#include <math.h>
#include <stdint.h>

// ---------------------------------------------------------------------------
// Problem constants
// ---------------------------------------------------------------------------
#define BATCH   8192
#define DIN     5169      // 1723*3
#define DINP    5184      // padded to 64
#define DH      1024
#define DOUT    226
#define DOUTP   256
#define EPS     1e-5f

// GEMM tiling: block 128x64, 256 threads (8 warps), warp tile 32x32 (4m x 2n)
// 2 blocks/SM co-residency: 96KB smem/block, <=128 regs/thread
#define BM      128
#define BN      64
#define BK      64
#define NTHREADS 256
#define OFF_A1  0
#define OFF_A2  16384
#define OFF_B1  32768
#define OFF_B2  40960
#define STAGE   49152
#define SMEM_REQ (2*STAGE)    // 96KB -> 2 blocks/SM

__device__ __forceinline__ uint32_t smem_u32(const void* p) {
    uint32_t a;
    asm("{ .reg .u64 t; cvta.to.shared.u64 t, %1; cvt.u32.u64 %0, t; }" : "=r"(a) : "l"(p));
    return a;
}

#define CPA16(dst, src) asm volatile("cp.async.cg.shared.global [%0], [%1], 16;" :: "r"(dst), "l"(src) : "memory")
#define CP_COMMIT() asm volatile("cp.async.commit_group;" ::: "memory")
#define CP_WAIT1()  asm volatile("cp.async.wait_group 1;" ::: "memory")
#define CP_WAIT0()  asm volatile("cp.async.wait_group 0;" ::: "memory")

#define LDSM4(r, addr) \
    asm volatile("ldmatrix.sync.aligned.m8n8.x4.shared.b16 {%0,%1,%2,%3}, [%4];" \
        : "=r"((r)[0]), "=r"((r)[1]), "=r"((r)[2]), "=r"((r)[3]) : "r"(addr))

#define MMA16816(c, a, b) \
    asm volatile("mma.sync.aligned.m16n8k16.row.col.f32.f16.f16.f32 " \
        "{%0,%1,%2,%3}, {%4,%5,%6,%7}, {%8,%9}, {%0,%1,%2,%3};" \
        : "+f"((c)[0]), "+f"((c)[1]), "+f"((c)[2]), "+f"((c)[3]) \
        : "r"((a)[0]), "r"((a)[1]), "r"((a)[2]), "r"((a)[3]), \
          "r"((b)[0]), "r"((b)[1]))

// ---------------------------------------------------------------------------
// Device scratch
// ---------------------------------------------------------------------------
__device__ float g_Y[BATCH * DH];
__device__ float g_O[BATCH * DOUT];
__device__ float g_stats[12 * DH];    // [layer][sum|sumsq][DH], 6 layers

// 2-way fp16 splits for activations
__device__ __half g_A01[BATCH * DINP];
__device__ __half g_A02[BATCH * DINP];
__device__ __half g_H1[BATCH * DH];
__device__ __half g_H2[BATCH * DH];
__device__ __half g_T1[BATCH * DH];
__device__ __half g_T2[BATCH * DH];

// 2-way fp16 splits for weights (transposed [N][K])
__device__ __half g_W0s[2][DH * DINP];
__device__ __half g_W1as[2][DH * DH];
__device__ __half g_W1bs[2][DH * DH];
__device__ __half g_W2as[2][DH * DH];
__device__ __half g_W2bs[2][DH * DH];
__device__ __half g_W3s[2][DOUTP * DH];

// ---------------------------------------------------------------------------
// Mega-prep: input split + all 6 weight transposes + stat zeroing, ONE kernel.
// ---------------------------------------------------------------------------
#define TB_SPLIT ((BATCH * DINP / 8 + 255) / 256)   // 20736
#define TB_W0   5184
#define TB_MID  1024
#define TB_W3   256
#define TB_ZERO 48
#define TB_TOTAL (TB_SPLIT + TB_W0 + 4*TB_MID + TB_W3 + TB_ZERO)

__device__ __forceinline__ void transpose_tile(
    const float* __restrict__ W, __half* __restrict__ s1, __half* __restrict__ s2,
    int K, int N, int Kpad, int tileKx, int localBid, int tx, int ty)
{
    __shared__ float sh[32][33];
    int kt = localBid % tileKx, nt = localBid / tileKx;
    int k0 = kt * 32, n0 = nt * 32;
#pragma unroll
    for (int p = 0; p < 4; p++) {
        int k = k0 + ty + p * 8, n = n0 + tx;
        sh[ty + p * 8][tx] = (k < K && n < N) ? W[(size_t)k * N + n] : 0.f;
    }
    __syncthreads();
#pragma unroll
    for (int p = 0; p < 4; p++) {
        int no = n0 + ty + p * 8, ko = k0 + tx;
        float v = sh[tx][ty + p * 8];
        __half h1 = __float2half(v);
        size_t idx = (size_t)no * Kpad + ko;
        s1[idx] = h1;
        s2[idx] = __float2half(v - __half2float(h1));
    }
}

__global__ void __launch_bounds__(256) mega_prep(
    const float* __restrict__ V,
    const float* __restrict__ W0, const float* __restrict__ W1a,
    const float* __restrict__ W1b, const float* __restrict__ W2a,
    const float* __restrict__ W2b, const float* __restrict__ W3)
{
    int bid = blockIdx.x;
    if (bid < TB_SPLIT) {
        int i = bid * 256 + threadIdx.x;
        int total8 = BATCH * DINP / 8;
        if (i >= total8) return;
        int cp8 = DINP >> 3;
        int r = i / cp8, c0 = (i - r * cp8) << 3;
        const float* row = V + (size_t)r * DIN;
        union { __half h[8]; uint4 u; } p1, p2;
#pragma unroll
        for (int k = 0; k < 8; k++) {
            int c = c0 + k;
            float v = (c < DIN) ? row[c] : 0.f;
            __half h1 = __float2half(v);
            p1.h[k] = h1;
            p2.h[k] = __float2half(v - __half2float(h1));
        }
        reinterpret_cast<uint4*>(g_A01)[i] = p1.u;
        reinterpret_cast<uint4*>(g_A02)[i] = p2.u;
        return;
    }
    bid -= TB_SPLIT;

    int tx = threadIdx.x & 31, ty = threadIdx.x >> 5;
    if (bid < TB_W0) {
        transpose_tile(W0, g_W0s[0], g_W0s[1], DIN, DH, DINP, DINP / 32, bid, tx, ty);
        return;
    }
    bid -= TB_W0;
    if (bid < TB_MID) {
        transpose_tile(W1a, g_W1as[0], g_W1as[1], DH, DH, DH, DH / 32, bid, tx, ty);
        return;
    }
    bid -= TB_MID;
    if (bid < TB_MID) {
        transpose_tile(W1b, g_W1bs[0], g_W1bs[1], DH, DH, DH, DH / 32, bid, tx, ty);
        return;
    }
    bid -= TB_MID;
    if (bid < TB_MID) {
        transpose_tile(W2a, g_W2as[0], g_W2as[1], DH, DH, DH, DH / 32, bid, tx, ty);
        return;
    }
    bid -= TB_MID;
    if (bid < TB_MID) {
        transpose_tile(W2b, g_W2bs[0], g_W2bs[1], DH, DH, DH, DH / 32, bid, tx, ty);
        return;
    }
    bid -= TB_MID;
    if (bid < TB_W3) {
        transpose_tile(W3, g_W3s[0], g_W3s[1], DH, DOUT, DH, DH / 32, bid, tx, ty);
        return;
    }
    bid -= TB_W3;
    int i = bid * 256 + threadIdx.x;
    if (i < 12 * DH) g_stats[i] = 0.f;
}

// ---------------------------------------------------------------------------
// mma.sync 2-split fp16 GEMM (2-stage, BM=128 x BN=64, 8 warps, occ=2):
//   C[M][ldC] = A(M x Kpad) * B^T(Npad x Kpad) + bias
// main acc: a1b1.  corr acc: a2b1, a1b2.
// End-of-chunk barrier hoisted after the LAST LDSM of the chunk so its
// drain overlaps the final k-step's MMAs (register-only work).
// Fused column stats via warp-shuffle reduction + global atomics.
// ---------------------------------------------------------------------------
__device__ __forceinline__ void prefetch_stage(
    uint32_t s0,
    const __half* __restrict__ A1, const __half* __restrict__ A2,
    const __half* __restrict__ B1, const __half* __restrict__ B2,
    int row0, int col0, size_t Kpad, size_t kb, int tid)
{
#pragma unroll
    for (int i = 0; i < 4; i++) {
        int idx = i * NTHREADS + tid;
        int r = idx >> 3, c8 = idx & 7;
        uint32_t dst = (uint32_t)(r * 128 + ((c8 ^ (r & 7)) << 4));
        size_t g = (size_t)(row0 + r) * Kpad + kb + (size_t)c8 * 8;
        CPA16(s0 + OFF_A1 + dst, A1 + g);
        CPA16(s0 + OFF_A2 + dst, A2 + g);
    }
#pragma unroll
    for (int i = 0; i < 2; i++) {
        int idx = i * NTHREADS + tid;
        int r = idx >> 3, c8 = idx & 7;
        uint32_t dst = (uint32_t)(r * 128 + ((c8 ^ (r & 7)) << 4));
        size_t g = (size_t)(col0 + r) * Kpad + kb + (size_t)c8 * 8;
        CPA16(s0 + OFF_B1 + dst, B1 + g);
        CPA16(s0 + OFF_B2 + dst, B2 + g);
    }
    CP_COMMIT();
}

__global__ void __launch_bounds__(NTHREADS, 2) gemm_mma_split2(
    const __half* __restrict__ A1, const __half* __restrict__ A2,
    const __half* __restrict__ B1, const __half* __restrict__ B2,
    const float* __restrict__ bias, float* __restrict__ C,
    int Kpad, int Nreal, int ldC,
    float* __restrict__ statSum, float* __restrict__ statSq)
{
    extern __shared__ char smraw[];
    const uint32_t sb = smem_u32(smraw);

    const int tid = threadIdx.x, wid = tid >> 5, lane = tid & 31;
    const int row0 = blockIdx.y * BM;
    const int col0 = blockIdx.x * BN;
    const int wm = (wid >> 1) * 32;
    const int wn = (wid & 1) * 32;
    const int T = Kpad / BK;

    float am[2][4][4];
    float ac[2][4][4];
#pragma unroll
    for (int i = 0; i < 2; i++)
#pragma unroll
        for (int j = 0; j < 4; j++)
#pragma unroll
            for (int v = 0; v < 4; v++) { am[i][j][v] = 0.f; ac[i][j][v] = 0.f; }

    const int la_r  = (lane & 7) + (lane & 8);
    const int la_kh = (lane & 16) ? 8 : 0;
    const int lb_r  = (lane & 7) + ((lane & 16) ? 8 : 0);
    const int lb_kh = (lane & 8) ? 8 : 0;

    prefetch_stage(sb, A1, A2, B1, B2, row0, col0, (size_t)Kpad, 0, tid);

    for (int t = 0; t < T; t++) {
        if (t + 1 < T) {
            prefetch_stage(sb + ((t + 1) & 1) * STAGE, A1, A2, B1, B2,
                           row0, col0, (size_t)Kpad, (size_t)(t + 1) * BK, tid);
            CP_WAIT1();
        } else {
            CP_WAIT0();
        }
        __syncthreads();

        const uint32_t s0 = sb + (t & 1) * STAGE;
#pragma unroll
        for (int ks = 0; ks < 4; ks++) {
            uint32_t a1[2][4], a2[2][4];
#pragma unroll
            for (int i = 0; i < 2; i++) {
                int r = wm + 16 * i + la_r;
                int k = ks * 16 + la_kh;
                uint32_t addr = s0 + OFF_A1 + r * 128 + ((((k >> 3) ^ r) & 7) << 4);
                LDSM4(a1[i], addr);
                LDSM4(a2[i], addr + (OFF_A2 - OFF_A1));
            }
            const int rB = wn + lb_r;
            const int kB = ks * 16 + lb_kh;
            const uint32_t baddr0 = s0 + OFF_B1 + rB * 128 + ((((kB >> 3) ^ rB) & 7) << 4);
            const uint32_t baddr1 = s0 + OFF_B1 + (rB + 16) * 128 + ((((kB >> 3) ^ (rB + 16)) & 7) << 4);

            {
                uint32_t b[4][2], q[4];
                LDSM4(q, baddr0);
                b[0][0]=q[0]; b[0][1]=q[1]; b[1][0]=q[2]; b[1][1]=q[3];
                LDSM4(q, baddr1);
                b[2][0]=q[0]; b[2][1]=q[1]; b[3][0]=q[2]; b[3][1]=q[3];
#pragma unroll
                for (int i = 0; i < 2; i++)
#pragma unroll
                    for (int j = 0; j < 4; j++) {
                        MMA16816(am[i][j], a1[i], b[j]);
                        MMA16816(ac[i][j], a2[i], b[j]);
                    }
            }
            {
                uint32_t b[4][2], q[4];
                LDSM4(q, baddr0 + (OFF_B2 - OFF_B1));
                b[0][0]=q[0]; b[0][1]=q[1]; b[1][0]=q[2]; b[1][1]=q[3];
                LDSM4(q, baddr1 + (OFF_B2 - OFF_B1));
                b[2][0]=q[0]; b[2][1]=q[1]; b[3][0]=q[2]; b[3][1]=q[3];
                // Last smem read of the chunk happened above for ks==3:
                // hoist the end-of-chunk barrier here so its drain overlaps
                // the final (register-only) MMA batch.
                if (ks == 3) __syncthreads();
#pragma unroll
                for (int i = 0; i < 2; i++)
#pragma unroll
                    for (int j = 0; j < 4; j++)
                        MMA16816(ac[i][j], a1[i], b[j]);
            }
        }
        // (end-of-chunk barrier already executed inside ks==3)
    }

    // epilogue
    const int gid = lane >> 2, tig = lane & 3;
    const bool doStats = (statSum != nullptr);
#pragma unroll
    for (int j = 0; j < 4; j++) {
        int cc = col0 + wn + 8 * j + tig * 2;
        float se = 0.f, so = 0.f, qe = 0.f, qo = 0.f;
        if (cc < Nreal) {
            float b0 = bias[cc], b1 = bias[cc + 1];
#pragma unroll
            for (int i = 0; i < 2; i++) {
                int r = row0 + wm + 16 * i + gid;
                float v00 = am[i][j][0] + ac[i][j][0] + b0;
                float v01 = am[i][j][1] + ac[i][j][1] + b1;
                float v10 = am[i][j][2] + ac[i][j][2] + b0;
                float v11 = am[i][j][3] + ac[i][j][3] + b1;
                *reinterpret_cast<float2*>(C + (size_t)r * ldC + cc) = make_float2(v00, v01);
                *reinterpret_cast<float2*>(C + (size_t)(r + 8) * ldC + cc) = make_float2(v10, v11);
                se += v00 + v10;
                so += v01 + v11;
                qe += fmaf(v00, v00, v10 * v10);
                qo += fmaf(v01, v01, v11 * v11);
            }
        }
        if (doStats) {
#pragma unroll
            for (int m = 4; m <= 16; m <<= 1) {
                se += __shfl_xor_sync(0xFFFFFFFFu, se, m);
                so += __shfl_xor_sync(0xFFFFFFFFu, so, m);
                qe += __shfl_xor_sync(0xFFFFFFFFu, qe, m);
                qo += __shfl_xor_sync(0xFFFFFFFFu, qo, m);
            }
            if (gid == 0) {
                atomicAdd(&statSum[cc],     se);
                atomicAdd(&statSum[cc + 1], so);
                atomicAdd(&statSq[cc],      qe);
                atomicAdd(&statSq[cc + 1],  qo);
            }
        }
    }
}

// ---------------------------------------------------------------------------
// Fused BN finalize + apply (4096 blocks x 2 rows, batched loads):
// ---------------------------------------------------------------------------
#define APPLY_BLOCKS 4096
#define APPLY_ROWS   (BATCH / APPLY_BLOCKS)   // 2

__global__ void __launch_bounds__(256) apply_bn_fused(
    const float4* __restrict__ Y4,
    const uint2* __restrict__ r1In,
    const uint2* __restrict__ r2In,
    uint2* __restrict__ o1,
    uint2* __restrict__ o2,
    const float* __restrict__ stat,
    const float* __restrict__ g,
    const float* __restrict__ be,
    int has_res)
{
    const int t = threadIdx.x;
    const int r0 = blockIdx.x * APPLY_ROWS;
    const int idx0 = r0 * (DH / 4) + t;
    const int idx1 = idx0 + (DH / 4);

    float4 y0 = Y4[idx0];
    float4 y1 = Y4[idx1];
    uint2 q10 = make_uint2(0u, 0u), q20 = make_uint2(0u, 0u);
    uint2 q11 = make_uint2(0u, 0u), q21 = make_uint2(0u, 0u);
    if (has_res) {
        q10 = r1In[idx0]; q20 = r2In[idx0];
        q11 = r1In[idx1]; q21 = r2In[idx1];
    }
    float4 sm = reinterpret_cast<const float4*>(stat)[t];
    float4 sq = reinterpret_cast<const float4*>(stat + DH)[t];
    float4 gg = reinterpret_cast<const float4*>(g)[t];
    float4 bb = reinterpret_cast<const float4*>(be)[t];

    const float invM = 1.f / (float)BATCH;
    float m0 = sm.x * invM, m1 = sm.y * invM, m2 = sm.z * invM, m3 = sm.w * invM;
    float a0 = gg.x * rsqrtf(sq.x * invM - m0 * m0 + EPS);
    float a1 = gg.y * rsqrtf(sq.y * invM - m1 * m1 + EPS);
    float a2 = gg.z * rsqrtf(sq.z * invM - m2 * m2 + EPS);
    float a3 = gg.w * rsqrtf(sq.w * invM - m3 * m3 + EPS);
    float c0 = bb.x - a0 * m0;
    float c1 = bb.y - a1 * m1;
    float c2 = bb.z - a2 * m2;
    float c3 = bb.w - a3 * m3;

    {
        union { __half h[4]; uint2 u; } q1, q2, p1, p2;
        q1.u = q10; q2.u = q20;
        float o[4];
        o[0] = fmaf(a0, y0.x, c0); o[1] = fmaf(a1, y0.y, c1);
        o[2] = fmaf(a2, y0.z, c2); o[3] = fmaf(a3, y0.w, c3);
        if (has_res) {
            o[0] += __half2float(q1.h[0]) + __half2float(q2.h[0]);
            o[1] += __half2float(q1.h[1]) + __half2float(q2.h[1]);
            o[2] += __half2float(q1.h[2]) + __half2float(q2.h[2]);
            o[3] += __half2float(q1.h[3]) + __half2float(q2.h[3]);
        }
#pragma unroll
        for (int v = 0; v < 4; v++) {
            float ov = fmaxf(0.f, o[v]);
            __half h1 = __float2half(ov);
            p1.h[v] = h1;
            p2.h[v] = __float2half(ov - __half2float(h1));
        }
        o1[idx0] = p1.u;
        o2[idx0] = p2.u;
    }
    {
        union { __half h[4]; uint2 u; } q1, q2, p1, p2;
        q1.u = q11; q2.u = q21;
        float o[4];
        o[0] = fmaf(a0, y1.x, c0); o[1] = fmaf(a1, y1.y, c1);
        o[2] = fmaf(a2, y1.z, c2); o[3] = fmaf(a3, y1.w, c3);
        if (has_res) {
            o[0] += __half2float(q1.h[0]) + __half2float(q2.h[0]);
            o[1] += __half2float(q1.h[1]) + __half2float(q2.h[1]);
            o[2] += __half2float(q1.h[2]) + __half2float(q2.h[2]);
            o[3] += __half2float(q1.h[3]) + __half2float(q2.h[3]);
        }
#pragma unroll
        for (int v = 0; v < 4; v++) {
            float ov = fmaxf(0.f, o[v]);
            __half h1 = __float2half(ov);
            p1.h[v] = h1;
            p2.h[v] = __float2half(ov - __half2float(h1));
        }
        o1[idx1] = p1.u;
        o2[idx1] = p2.u;
    }
}

// ---------------------------------------------------------------------------
// Polar decomposition of 3x3 (== U*Vh), times sign(det) + betas passthrough
// ---------------------------------------------------------------------------
__device__ __forceinline__ void cof3(const float* X, float* C) {
    C[0] = X[4]*X[8] - X[5]*X[7];
    C[1] = X[5]*X[6] - X[3]*X[8];
    C[2] = X[3]*X[7] - X[4]*X[6];
    C[3] = X[2]*X[7] - X[1]*X[8];
    C[4] = X[0]*X[8] - X[2]*X[6];
    C[5] = X[1]*X[6] - X[0]*X[7];
    C[6] = X[1]*X[5] - X[2]*X[4];
    C[7] = X[2]*X[3] - X[0]*X[5];
    C[8] = X[0]*X[4] - X[1]*X[3];
}

__global__ void polar_betas_kernel(const float* __restrict__ O, float* __restrict__ out) {
    int n = blockIdx.x * blockDim.x + threadIdx.x;
    if (n >= BATCH * 24) {
        int i = n - BATCH * 24;
        if (i < BATCH * 10) {
            int r = i / 10, j = i % 10;
            out[(size_t)BATCH * 216 + i] = O[(size_t)r * DOUT + 216 + j];
        }
        return;
    }
    int r = n / 24, m = n % 24;
    const float* src = O + (size_t)r * DOUT + m * 9;
    float X[9];
#pragma unroll
    for (int i = 0; i < 9; i++) X[i] = src[i];

    float C[9];
    cof3(X, C);
    float det0 = X[0]*C[0] + X[1]*C[1] + X[2]*C[2];
    float sgn = (det0 >= 0.f) ? 1.f : -1.f;

    float fro = 0.f;
#pragma unroll
    for (int i = 0; i < 9; i++) fro = fmaf(X[i], X[i], fro);
    float inv = rsqrtf(fmaxf(fro, 1e-30f));
#pragma unroll
    for (int i = 0; i < 9; i++) X[i] *= inv;

#pragma unroll
    for (int it = 0; it < 12; it++) {
        cof3(X, C);
        float det = X[0]*C[0] + X[1]*C[1] + X[2]*C[2];
        float adet = fabsf(det);
        if (adet < 1e-30f) break;
        float gscale = rcbrtf(adet);
        float invdet = 1.f / det;
        float ig = 0.5f * invdet / gscale;
        float hg = 0.5f * gscale;
#pragma unroll
        for (int i = 0; i < 9; i++) X[i] = hg * X[i] + ig * C[i];
    }

    float* dst = out + (size_t)n * 9;
#pragma unroll
    for (int i = 0; i < 9; i++) dst[i] = X[i] * sgn;
}

// ---------------------------------------------------------------------------
// Launch
// ---------------------------------------------------------------------------
extern "C" void kernel_launch(void* const* d_in, const int* in_sizes, int n_in,
                              void* d_out, int out_size)
{
    const float* V   = (const float*)d_in[0];
    const float* W0  = (const float*)d_in[1];
    const float* b0  = (const float*)d_in[2];
    const float* g0  = (const float*)d_in[3];
    const float* be0 = (const float*)d_in[4];
    const float* W1a = (const float*)d_in[5];
    const float* b1a = (const float*)d_in[6];
    const float* g1a = (const float*)d_in[7];
    const float* be1a= (const float*)d_in[8];
    const float* W1b = (const float*)d_in[9];
    const float* b1b = (const float*)d_in[10];
    const float* g1b = (const float*)d_in[11];
    const float* be1b= (const float*)d_in[12];
    const float* W2a = (const float*)d_in[13];
    const float* b2a = (const float*)d_in[14];
    const float* g2a = (const float*)d_in[15];
    const float* be2a= (const float*)d_in[16];
    const float* W2b = (const float*)d_in[17];
    const float* b2b = (const float*)d_in[18];
    const float* g2b = (const float*)d_in[19];
    const float* be2b= (const float*)d_in[20];
    const float* W3  = (const float*)d_in[21];
    const float* b3  = (const float*)d_in[22];

    float *Y, *O, *ST;
    cudaGetSymbolAddress((void**)&Y, g_Y);
    cudaGetSymbolAddress((void**)&O, g_O);
    cudaGetSymbolAddress((void**)&ST, g_stats);

    __half *A0s[2], *Hs[2], *Ts[2];
    __half *W0p[2], *W1ap[2], *W1bp[2], *W2ap[2], *W2bp[2], *W3p[2];
    {
        __half* base;
        cudaGetSymbolAddress((void**)&base, g_A01); A0s[0] = base;
        cudaGetSymbolAddress((void**)&base, g_A02); A0s[1] = base;
        cudaGetSymbolAddress((void**)&base, g_H1);  Hs[0] = base;
        cudaGetSymbolAddress((void**)&base, g_H2);  Hs[1] = base;
        cudaGetSymbolAddress((void**)&base, g_T1);  Ts[0] = base;
        cudaGetSymbolAddress((void**)&base, g_T2);  Ts[1] = base;
        cudaGetSymbolAddress((void**)&base, g_W0s);
        W0p[0] = base; W0p[1] = base + (size_t)DH * DINP;
        cudaGetSymbolAddress((void**)&base, g_W1as);
        W1ap[0] = base; W1ap[1] = base + (size_t)DH * DH;
        cudaGetSymbolAddress((void**)&base, g_W1bs);
        W1bp[0] = base; W1bp[1] = base + (size_t)DH * DH;
        cudaGetSymbolAddress((void**)&base, g_W2as);
        W2ap[0] = base; W2ap[1] = base + (size_t)DH * DH;
        cudaGetSymbolAddress((void**)&base, g_W2bs);
        W2bp[0] = base; W2bp[1] = base + (size_t)DH * DH;
        cudaGetSymbolAddress((void**)&base, g_W3s);
        W3p[0] = base; W3p[1] = base + (size_t)DOUTP * DH;
    }

    cudaFuncSetAttribute(gemm_mma_split2, cudaFuncAttributeMaxDynamicSharedMemorySize, SMEM_REQ);

    // ---- prep: ONE kernel (input split + weight transposes + stat zero) ----
    mega_prep<<<TB_TOTAL, 256>>>(V, W0, W1a, W1b, W2a, W2b, W3);

    const dim3 gGrid(DH / BN, BATCH / BM);       // (16, 64) = 1024 blocks
    const dim3 gGrid3(DOUTP / BN, BATCH / BM);   // (4, 64)  = 256 blocks

    // layer 0
    gemm_mma_split2<<<gGrid, NTHREADS, SMEM_REQ>>>(A0s[0], A0s[1], W0p[0], W0p[1], b0, Y,
                                                   DINP, DH, DH, ST + 0 * 2 * DH, ST + (0 * 2 + 1) * DH);
    apply_bn_fused<<<APPLY_BLOCKS, 256>>>((const float4*)Y, nullptr, nullptr,
                                          (uint2*)Hs[0], (uint2*)Hs[1],
                                          ST + 0 * 2 * DH, g0, be0, 0);
    // block 1
    gemm_mma_split2<<<gGrid, NTHREADS, SMEM_REQ>>>(Hs[0], Hs[1], W1ap[0], W1ap[1], b1a, Y,
                                                   DH, DH, DH, ST + 1 * 2 * DH, ST + (1 * 2 + 1) * DH);
    apply_bn_fused<<<APPLY_BLOCKS, 256>>>((const float4*)Y, nullptr, nullptr,
                                          (uint2*)Ts[0], (uint2*)Ts[1],
                                          ST + 1 * 2 * DH, g1a, be1a, 0);
    gemm_mma_split2<<<gGrid, NTHREADS, SMEM_REQ>>>(Ts[0], Ts[1], W1bp[0], W1bp[1], b1b, Y,
                                                   DH, DH, DH, ST + 2 * 2 * DH, ST + (2 * 2 + 1) * DH);
    apply_bn_fused<<<APPLY_BLOCKS, 256>>>((const float4*)Y, (const uint2*)Hs[0], (const uint2*)Hs[1],
                                          (uint2*)Hs[0], (uint2*)Hs[1],
                                          ST + 2 * 2 * DH, g1b, be1b, 1);
    // block 2
    gemm_mma_split2<<<gGrid, NTHREADS, SMEM_REQ>>>(Hs[0], Hs[1], W2ap[0], W2ap[1], b2a, Y,
                                                   DH, DH, DH, ST + 3 * 2 * DH, ST + (3 * 2 + 1) * DH);
    apply_bn_fused<<<APPLY_BLOCKS, 256>>>((const float4*)Y, nullptr, nullptr,
                                          (uint2*)Ts[0], (uint2*)Ts[1],
                                          ST + 3 * 2 * DH, g2a, be2a, 0);
    gemm_mma_split2<<<gGrid, NTHREADS, SMEM_REQ>>>(Ts[0], Ts[1], W2bp[0], W2bp[1], b2b, Y,
                                                   DH, DH, DH, ST + 4 * 2 * DH, ST + (4 * 2 + 1) * DH);
    apply_bn_fused<<<APPLY_BLOCKS, 256>>>((const float4*)Y, (const uint2*)Hs[0], (const uint2*)Hs[1],
                                          (uint2*)Hs[0], (uint2*)Hs[1],
                                          ST + 4 * 2 * DH, g2b, be2b, 1);
    // head (no stats)
    gemm_mma_split2<<<gGrid3, NTHREADS, SMEM_REQ>>>(Hs[0], Hs[1], W3p[0], W3p[1], b3, O,
                                                    DH, DOUT, DOUT, nullptr, nullptr);

    polar_betas_kernel<<<(BATCH * 24 + BATCH * 10 + 255) / 256, 256>>>(O, (float*)d_out);
}